// round 1
// baseline (speedup 1.0000x reference)
#include <cuda_runtime.h>
#include <cstdint>

#define NEG_INIT -1.0e9f

// ---------------------------------------------------------------------------
// float <-> order-preserving unsigned encoding (for atomicMax on floats)
// ---------------------------------------------------------------------------
__device__ __forceinline__ unsigned enc_f(float f) {
    unsigned u = __float_as_uint(f);
    return (u & 0x80000000u) ? ~u : (u | 0x80000000u);
}
__device__ __forceinline__ float dec_f(unsigned e) {
    unsigned u = (e & 0x80000000u) ? (e & 0x7FFFFFFFu) : ~e;
    return __uint_as_float(u);
}

__device__ __forceinline__ float lrelu(float x) {
    return x >= 0.f ? x : 0.2f * x;
}

// Scratch: encoded global_feats[B,128], B <= 16384. 8 MB static device array.
__device__ unsigned g_gf[16384 * 128];

// ---------------------------------------------------------------------------
// Kernel 0: init encoded global feats to enc(-1e9)
// ---------------------------------------------------------------------------
__global__ void init_gf_kernel(int total) {
    int i = blockIdx.x * blockDim.x + threadIdx.x;
    if (i < total) g_gf[i] = enc_f(NEG_INIT);
}

// ---------------------------------------------------------------------------
// Kernel A: fused point MLP (layer1 + layer2) + block-local segmented max
//   grid.x = ceil(N/128), block = 256 threads
//   dynamic smem: 105,472 bytes
// ---------------------------------------------------------------------------
__global__ __launch_bounds__(256, 2) void point_kernel(
    const float* __restrict__ fm,     // [N,3]
    const int*   __restrict__ bidx,   // [N] sorted
    const float* __restrict__ cond,   // [B,4]
    const float* __restrict__ W1,     // [7,64]
    const float* __restrict__ b1,     // [64]
    const float* __restrict__ W2,     // [64,128]
    const float* __restrict__ b2,     // [128]
    int N)
{
    extern __shared__ float smem[];
    float* W2s = smem;                  // 64*128 = 8192 floats
    float* uni = smem + 8192;           // union: h_s (64*128) / os (128*136)
    float* h_s = uni;                   // [64][128] K-major activations
    float* os  = uni;                   // [128][136] lrelu(point_feats) tile
    float* W1s = uni + 17408;           // 448
    float* b1s = W1s + 448;             // 64
    float* b2s = b1s + 64;              // 128
    int*   bidx_s = (int*)(b2s + 128);  // 128

    const int t = threadIdx.x;

    // --- stage weights into shared ---
    {
        const float4* src = (const float4*)W2;
        float4* dst = (float4*)W2s;
        #pragma unroll
        for (int i = 0; i < 8; i++) dst[t + i * 256] = src[t + i * 256];
    }
    for (int i = t; i < 448; i += 256) W1s[i] = W1[i];
    if (t < 64)  b1s[t] = b1[t];
    if (t < 128) b2s[t] = b2[t];

    // --- load this thread's point inputs (two threads per point) ---
    const int m0   = blockIdx.x * 128;
    const int m    = t & 127;
    const int half = t >> 7;
    const int row  = m0 + m;
    float in[7];
    int b = -1;
    if (row < N) {
        in[0] = fm[row * 3 + 0];
        in[1] = fm[row * 3 + 1];
        in[2] = fm[row * 3 + 2];
        b = bidx[row];
        in[3] = cond[b * 4 + 0];
        in[4] = cond[b * 4 + 1];
        in[5] = cond[b * 4 + 2];
        in[6] = cond[b * 4 + 3];
    } else {
        #pragma unroll
        for (int k = 0; k < 7; k++) in[k] = 0.f;
    }
    if (half == 0) bidx_s[m] = b;
    __syncthreads();   // weights + bidx_s ready

    // --- layer 1: h[m][j] = lrelu(in . W1[:,j] + b1[j]), stored K-major ---
    #pragma unroll
    for (int jj = 0; jj < 32; jj++) {
        const int j = half * 32 + jj;
        float acc = b1s[j];
        #pragma unroll
        for (int k = 0; k < 7; k++) acc += in[k] * W1s[k * 64 + j];
        h_s[j * 128 + m] = lrelu(acc);
    }
    __syncthreads();   // h_s ready

    // --- layer 2: 128x128x64 GEMM, 8x8 register tile per thread ---
    const int tx = t & 15;
    const int ty = t >> 4;
    float acc[8][8];
    #pragma unroll
    for (int i = 0; i < 8; i++)
        #pragma unroll
        for (int j = 0; j < 8; j++) acc[i][j] = 0.f;

    #pragma unroll 2
    for (int k = 0; k < 64; k++) {
        float4 a0 = *(const float4*)(h_s + k * 128 + ty * 8);
        float4 a1 = *(const float4*)(h_s + k * 128 + ty * 8 + 4);
        float4 w0 = *(const float4*)(W2s + k * 128 + tx * 8);
        float4 w1 = *(const float4*)(W2s + k * 128 + tx * 8 + 4);
        float a[8] = {a0.x, a0.y, a0.z, a0.w, a1.x, a1.y, a1.z, a1.w};
        float w[8] = {w0.x, w0.y, w0.z, w0.w, w1.x, w1.y, w1.z, w1.w};
        #pragma unroll
        for (int i = 0; i < 8; i++)
            #pragma unroll
            for (int j = 0; j < 8; j++)
                acc[i][j] += a[i] * w[j];
    }
    __syncthreads();   // all h_s reads done before os overwrite (union!)

    // --- epilogue: bias + lrelu -> os tile ---
    float bb[8];
    #pragma unroll
    for (int j = 0; j < 8; j++) bb[j] = b2s[tx * 8 + j];
    #pragma unroll
    for (int i = 0; i < 8; i++) {
        const int mm = ty * 8 + i;
        float4 v0, v1;
        v0.x = lrelu(acc[i][0] + bb[0]);
        v0.y = lrelu(acc[i][1] + bb[1]);
        v0.z = lrelu(acc[i][2] + bb[2]);
        v0.w = lrelu(acc[i][3] + bb[3]);
        v1.x = lrelu(acc[i][4] + bb[4]);
        v1.y = lrelu(acc[i][5] + bb[5]);
        v1.z = lrelu(acc[i][6] + bb[6]);
        v1.w = lrelu(acc[i][7] + bb[7]);
        *(float4*)(os + mm * 136 + tx * 8)     = v0;
        *(float4*)(os + mm * 136 + tx * 8 + 4) = v1;
    }
    __syncthreads();

    // --- segmented max over the 128 (sorted) rows, one thread per feature ---
    if (t < 128) {
        const int c = t;
        float run = NEG_INIT;
        int prev = bidx_s[0];
        for (int r = 0; r < 128; r++) {
            const int brow = bidx_s[r];
            if (brow != prev) {
                if (prev >= 0) atomicMax(&g_gf[prev * 128 + c], enc_f(run));
                run = NEG_INIT;
                prev = brow;
            }
            run = fmaxf(run, os[r * 136 + c]);
        }
        if (prev >= 0) atomicMax(&g_gf[prev * 128 + c], enc_f(run));
    }
}

// ---------------------------------------------------------------------------
// Kernel B: decision MLP, 16 batches per block, 128 threads
//   dynamic smem: 85,248 bytes
// ---------------------------------------------------------------------------
__global__ __launch_bounds__(128) void decision_kernel(
    const float* __restrict__ cond,   // [B,4]
    const float* __restrict__ W3,     // [132,128]
    const float* __restrict__ b3,     // [128]
    const float* __restrict__ W4,     // [128,1]
    const float* __restrict__ b4,     // [1]
    float* __restrict__ out,          // [B]
    int B)
{
    extern __shared__ float smem[];
    float* W3s   = smem;              // 132*128 = 16896
    float* b3s   = W3s + 16896;       // 128
    float* W4s   = b3s + 128;         // 128
    float* in_s  = W4s + 128;         // 16*132 = 2112
    float* hid_s = in_s + 2112;       // 16*128 = 2048

    const int t = threadIdx.x;

    {   // copy W3 (4224 float4)
        const float4* src = (const float4*)W3;
        float4* dst = (float4*)W3s;
        for (int i = t; i < 4224; i += 128) dst[i] = src[i];
    }
    b3s[t] = b3[t];
    W4s[t] = W4[t];

    const int b0 = blockIdx.x * 16;
    for (int i = t; i < 16 * 132; i += 128) {
        const int bi = i / 132;
        const int k  = i % 132;
        const int bb = b0 + bi;
        float v = 0.f;
        if (bb < B)
            v = (k < 128) ? dec_f(g_gf[bb * 128 + k]) : cond[bb * 4 + (k - 128)];
        in_s[bi * 132 + k] = v;
    }
    __syncthreads();

    // hidden layer: thread t = output unit j, loop over 16 batches
    const int j = t;
    for (int i = 0; i < 16; i++) {
        float acc = b3s[j];
        #pragma unroll 4
        for (int k = 0; k < 132; k++)
            acc += in_s[i * 132 + k] * W3s[k * 128 + j];
        hid_s[i * 128 + j] = lrelu(acc);
    }
    __syncthreads();

    // final dot with W4: 8 threads cooperate per batch
    const int i = t >> 3;    // batch within block: 0..15
    const int g = t & 7;     // group lane: 0..7
    float acc = 0.f;
    #pragma unroll
    for (int q = 0; q < 16; q++) {
        const int jj = g * 16 + q;
        acc += hid_s[i * 128 + jj] * W4s[jj];
    }
    acc += __shfl_down_sync(0xFFFFFFFFu, acc, 4, 8);
    acc += __shfl_down_sync(0xFFFFFFFFu, acc, 2, 8);
    acc += __shfl_down_sync(0xFFFFFFFFu, acc, 1, 8);
    if (g == 0 && (b0 + i) < B) out[b0 + i] = acc + b4[0];
}

// ---------------------------------------------------------------------------
// Launch
// ---------------------------------------------------------------------------
extern "C" void kernel_launch(void* const* d_in, const int* in_sizes, int n_in,
                              void* d_out, int out_size)
{
    const float* fm   = (const float*)d_in[0];
    const int*   bi   = (const int*)  d_in[1];
    const float* cond = (const float*)d_in[2];
    // batch_size may or may not appear as a 4th input array
    const int base = (n_in >= 12) ? 4 : 3;
    const float* W1 = (const float*)d_in[base + 0];
    const float* b1 = (const float*)d_in[base + 1];
    const float* W2 = (const float*)d_in[base + 2];
    const float* b2 = (const float*)d_in[base + 3];
    const float* W3 = (const float*)d_in[base + 4];
    const float* b3 = (const float*)d_in[base + 5];
    const float* W4 = (const float*)d_in[base + 6];
    const float* b4 = (const float*)d_in[base + 7];

    const int N = in_sizes[0] / 3;
    const int B = in_sizes[2] / 4;
    float* out = (float*)d_out;

    const int SMEM_A = 26368 * 4;   // 105,472 B
    const int SMEM_B = 21312 * 4;   //  85,248 B
    cudaFuncSetAttribute(point_kernel,
                         cudaFuncAttributeMaxDynamicSharedMemorySize, SMEM_A);
    cudaFuncSetAttribute(decision_kernel,
                         cudaFuncAttributeMaxDynamicSharedMemorySize, SMEM_B);

    const int total_gf = B * 128;
    init_gf_kernel<<<(total_gf + 255) / 256, 256>>>(total_gf);

    const int gridA = (N + 127) / 128;
    point_kernel<<<gridA, 256, SMEM_A>>>(fm, bi, cond, W1, b1, W2, b2, N);

    const int gridB = (B + 15) / 16;
    decision_kernel<<<gridB, 128, SMEM_B>>>(cond, W3, b3, W4, b4, out, B);
}

// round 3
// speedup vs baseline: 1.6928x; 1.6928x over previous
#include <cuda_runtime.h>
#include <cuda_bf16.h>
#include <cstdint>

#define NEG_INIT -1.0e9f

// ---------------------------------------------------------------------------
__device__ __forceinline__ unsigned enc_f(float f) {
    unsigned u = __float_as_uint(f);
    return (u & 0x80000000u) ? ~u : (u | 0x80000000u);
}
__device__ __forceinline__ float dec_f(unsigned e) {
    unsigned u = (e & 0x80000000u) ? (e & 0x7FFFFFFFu) : ~e;
    return __uint_as_float(u);
}
__device__ __forceinline__ float lrelu(float x) { return x >= 0.f ? x : 0.2f * x; }

__device__ unsigned g_gf[16384 * 128];   // encoded global_feats scratch (8 MB)

__device__ __forceinline__ uint32_t smem_u32(const void* p) {
    uint32_t a;
    asm("{ .reg .u64 t; cvta.to.shared.u64 t, %1; cvt.u32.u64 %0, t; }" : "=r"(a) : "l"(p));
    return a;
}

#define SWZ(x) ((x) ^ (((x) >> 3) & 0x70))

__device__ __forceinline__ void ldsm4(unsigned r[4], uint32_t addr) {
    asm volatile("ldmatrix.sync.aligned.m8n8.x4.shared.b16 {%0,%1,%2,%3}, [%4];"
                 : "=r"(r[0]), "=r"(r[1]), "=r"(r[2]), "=r"(r[3]) : "r"(addr));
}
__device__ __forceinline__ void hmma(float d[4], const unsigned a[4],
                                     unsigned b0, unsigned b1) {
    asm volatile(
        "mma.sync.aligned.m16n8k16.row.col.f32.bf16.bf16.f32 "
        "{%0,%1,%2,%3}, {%4,%5,%6,%7}, {%8,%9}, {%0,%1,%2,%3};"
        : "+f"(d[0]), "+f"(d[1]), "+f"(d[2]), "+f"(d[3])
        : "r"(a[0]), "r"(a[1]), "r"(a[2]), "r"(a[3]), "r"(b0), "r"(b1));
}

__device__ __forceinline__ unsigned pack_bf16(float a, float b) {
    __nv_bfloat16 ha = __float2bfloat16(a), hb = __float2bfloat16(b);
    return ((unsigned)__bfloat16_as_ushort(hb) << 16) | __bfloat16_as_ushort(ha);
}

// ---------------------------------------------------------------------------
// SMEM layout (bytes)
// ---------------------------------------------------------------------------
#define OFF_BHI   0          // [128n][64k] bf16, SW128, 16384 B
#define OFF_BLO   16384
#define OFF_AHI   32768      // [128m][64k] bf16, SW128  (overlaid by os)
#define OFF_ALO   49152
#define OFF_OS    32768      // [128][130] float (66560 B), overlays A
#define OFF_W1    99328      // 448 floats
#define OFF_B1    101120     // 64 floats
#define OFF_B2    101376     // 128 floats
#define OFF_BIDX  101888     // 128 ints
#define OFF_COND  102400     // 128*4 floats
#define OFF_FM    104448     // 128*3 floats
#define SMEM_BYTES 105984

// ---------------------------------------------------------------------------
__global__ void init_gf_kernel(int total) {
    int i = blockIdx.x * blockDim.x + threadIdx.x;
    if (i < total) g_gf[i] = enc_f(NEG_INIT);
}

// ---------------------------------------------------------------------------
// Persistent fused point kernel: layer1 (FFMA) + layer2 (HMMA bf16-split)
// + segmented max.  256 threads, grid = 296.
// ---------------------------------------------------------------------------
__global__ __launch_bounds__(256, 2) void point_kernel(
    const float* __restrict__ fm,   const int* __restrict__ bidx,
    const float* __restrict__ cond, const float* __restrict__ W1,
    const float* __restrict__ b1,   const float* __restrict__ W2,
    const float* __restrict__ b2,   int N, int numTiles)
{
    extern __shared__ char smem[];
    const uint32_t sbase = smem_u32(smem);
    const int t    = threadIdx.x;
    const int wid  = t >> 5;
    const int lane = t & 31;

    float* W1s   = (float*)(smem + OFF_W1);
    float* b1s   = (float*)(smem + OFF_B1);
    float* b2s   = (float*)(smem + OFF_B2);
    int*   bix   = (int*)(smem + OFF_BIDX);
    float* conds = (float*)(smem + OFF_COND);
    float* fms   = (float*)(smem + OFF_FM);
    float* os    = (float*)(smem + OFF_OS);

    // ---- one-time staging: W2 -> B hi/lo ([n][k] bf16, SW128), W1, biases ----
    for (int e = t; e < 4096; e += 256) {
        int n = e >> 5, k2 = e & 31;                 // k2 indexes pairs of k
        float w0 = W2[(2 * k2) * 128 + n];
        float w1 = W2[(2 * k2 + 1) * 128 + n];
        __nv_bfloat16 h0 = __float2bfloat16(w0), h1 = __float2bfloat16(w1);
        float r0 = w0 - __bfloat162float(h0), r1 = w1 - __bfloat162float(h1);
        unsigned hi = ((unsigned)__bfloat16_as_ushort(h1) << 16) | __bfloat16_as_ushort(h0);
        unsigned lo = pack_bf16(r0, r1);
        unsigned off = (unsigned)(n * 128 + k2 * 4);
        *(unsigned*)(smem + OFF_BHI + SWZ(off)) = hi;
        *(unsigned*)(smem + OFF_BLO + SWZ(off)) = lo;
    }
    for (int i = t; i < 448; i += 256) W1s[i] = W1[i];
    if (t < 64)  b1s[t] = b1[t];
    if (t < 128) b2s[t] = b2[t];

    const int m    = t & 127;
    const int half = t >> 7;
    const int wm   = wid & 3;      // m 32-slice
    const int wn   = wid >> 2;     // n 64-slice

    for (int tile = blockIdx.x; tile < numTiles; tile += gridDim.x) {
        const int rbase = tile * 128;
        __syncthreads();           // prior scan reads done (os/bix reuse)

        // ---- phase A: stage inputs ----
        for (int i = t; i < 384; i += 256) {
            int g = rbase * 3 + i;
            fms[i] = (g < N * 3) ? fm[g] : 0.f;
        }
        if (t < 128) {
            int row = rbase + t;
            int b = (row < N) ? bidx[row] : -1;
            bix[t] = b;
            float4 c4 = make_float4(0.f, 0.f, 0.f, 0.f);
            if (b >= 0) c4 = *(const float4*)(cond + b * 4);
            *(float4*)(conds + t * 4) = c4;
        }
        __syncthreads();

        // ---- phase B: layer 1 (each thread: row m, 32 cols) ----
        {
            float in[7];
            in[0] = fms[m * 3 + 0]; in[1] = fms[m * 3 + 1]; in[2] = fms[m * 3 + 2];
            in[3] = conds[m * 4 + 0]; in[4] = conds[m * 4 + 1];
            in[5] = conds[m * 4 + 2]; in[6] = conds[m * 4 + 3];
            float h[32];
            #pragma unroll
            for (int jj = 0; jj < 32; jj++) {
                const int j = (half << 5) + jj;
                float a = b1s[j];
                #pragma unroll
                for (int k = 0; k < 7; k++) a += in[k] * W1s[k * 64 + j];
                h[jj] = lrelu(a);
            }
            // split + store A hi/lo (STS.128, swizzled, conflict-free)
            #pragma unroll
            for (int q = 0; q < 4; q++) {
                uint4 uhi, ulo;
                float hv[8], lv[8];
                #pragma unroll
                for (int e = 0; e < 8; e++) {
                    float x = h[q * 8 + e];
                    __nv_bfloat16 hb = __float2bfloat16(x);
                    hv[e] = __bfloat162float(hb);
                    lv[e] = x - hv[e];
                }
                uhi.x = pack_bf16(hv[0], hv[1]); uhi.y = pack_bf16(hv[2], hv[3]);
                uhi.z = pack_bf16(hv[4], hv[5]); uhi.w = pack_bf16(hv[6], hv[7]);
                ulo.x = pack_bf16(lv[0], lv[1]); ulo.y = pack_bf16(lv[2], lv[3]);
                ulo.z = pack_bf16(lv[4], lv[5]); ulo.w = pack_bf16(lv[6], lv[7]);
                const int chunk = ((half << 2) + q) ^ (m & 7);
                *(uint4*)(smem + OFF_AHI + m * 128 + (chunk << 4)) = uhi;
                *(uint4*)(smem + OFF_ALO + m * 128 + (chunk << 4)) = ulo;
            }
        }
        __syncthreads();

        // ---- phase C: layer 2 GEMM (HMMA, bf16 split x3) ----
        float d[2][8][4];
        #pragma unroll
        for (int mi = 0; mi < 2; mi++)
            #pragma unroll
            for (int ni = 0; ni < 8; ni++)
                #pragma unroll
                for (int e = 0; e < 4; e++) d[mi][ni][e] = 0.f;

        #pragma unroll
        for (int ks = 0; ks < 4; ks++) {
            // A fragment addresses (m16k16 tiles)
            int arow = (wm << 5) + (lane & 15);
            int akch = (ks << 1) + (lane >> 4);
            uint32_t aoff = (uint32_t)(arow * 128 + (((akch ^ (arow & 7)) & 7) << 4));
            unsigned ahi[2][4], alo[2][4];
            ldsm4(ahi[0], sbase + OFF_AHI + aoff);
            ldsm4(ahi[1], sbase + OFF_AHI + aoff + 16 * 128);
            ldsm4(alo[0], sbase + OFF_ALO + aoff);
            ldsm4(alo[1], sbase + OFF_ALO + aoff + 16 * 128);
            // B fragments (n16k16 tiles), hi first
            int brow = (wn << 6) + (lane & 7) + ((lane >> 4) << 3);
            int bkch = (ks << 1) + ((lane >> 3) & 1);
            uint32_t boff = (uint32_t)(brow * 128 + (((bkch ^ (brow & 7)) & 7) << 4));
            unsigned bf[4][4];
            #pragma unroll
            for (int g = 0; g < 4; g++) ldsm4(bf[g], sbase + OFF_BHI + boff + g * 2048);
            #pragma unroll
            for (int g = 0; g < 4; g++) {
                #pragma unroll
                for (int mi = 0; mi < 2; mi++) {
                    hmma(d[mi][2 * g + 0], ahi[mi], bf[g][0], bf[g][1]);
                    hmma(d[mi][2 * g + 1], ahi[mi], bf[g][2], bf[g][3]);
                    hmma(d[mi][2 * g + 0], alo[mi], bf[g][0], bf[g][1]);
                    hmma(d[mi][2 * g + 1], alo[mi], bf[g][2], bf[g][3]);
                }
            }
            // B lo
            #pragma unroll
            for (int g = 0; g < 4; g++) ldsm4(bf[g], sbase + OFF_BLO + boff + g * 2048);
            #pragma unroll
            for (int g = 0; g < 4; g++) {
                #pragma unroll
                for (int mi = 0; mi < 2; mi++) {
                    hmma(d[mi][2 * g + 0], ahi[mi], bf[g][0], bf[g][1]);
                    hmma(d[mi][2 * g + 1], ahi[mi], bf[g][2], bf[g][3]);
                }
            }
        }
        __syncthreads();   // A reads done before os overwrite

        // ---- phase D: store D fragments to os [128][130] ----
        #pragma unroll
        for (int mi = 0; mi < 2; mi++) {
            const int r0 = (wm << 5) + (mi << 4) + (lane >> 2);
            #pragma unroll
            for (int ni = 0; ni < 8; ni++) {
                const int c = (wn << 6) + (ni << 3) + ((lane & 3) << 1);
                *(float2*)(os + r0 * 130 + c)       = make_float2(d[mi][ni][0], d[mi][ni][1]);
                *(float2*)(os + (r0 + 8) * 130 + c) = make_float2(d[mi][ni][2], d[mi][ni][3]);
            }
        }
        __syncthreads();

        // ---- phase E: segmented max scan (thread = (col, half), 64 rows) ----
        {
            const int c = t & 127;
            const int r0 = half << 6;
            float run = NEG_INIT;
            int prev = bix[r0];
            #pragma unroll 4
            for (int r = r0; r < r0 + 64; r++) {
                const int b = bix[r];
                if (b != prev) {
                    if (prev >= 0)
                        atomicMax(&g_gf[(prev << 7) + c], enc_f(lrelu(run + b2s[c])));
                    run = NEG_INIT;
                    prev = b;
                }
                run = fmaxf(run, os[r * 130 + c]);
            }
            if (prev >= 0)
                atomicMax(&g_gf[(prev << 7) + c], enc_f(lrelu(run + b2s[c])));
        }
    }
}

// ---------------------------------------------------------------------------
// Decision MLP (unchanged)
// ---------------------------------------------------------------------------
__global__ __launch_bounds__(128) void decision_kernel(
    const float* __restrict__ cond, const float* __restrict__ W3,
    const float* __restrict__ b3,   const float* __restrict__ W4,
    const float* __restrict__ b4,   float* __restrict__ out, int B)
{
    extern __shared__ float sm[];
    float* W3s   = sm;
    float* b3s   = W3s + 16896;
    float* W4s   = b3s + 128;
    float* in_s  = W4s + 128;
    float* hid_s = in_s + 2112;

    const int t = threadIdx.x;
    {
        const float4* src = (const float4*)W3;
        float4* dst = (float4*)W3s;
        for (int i = t; i < 4224; i += 128) dst[i] = src[i];
    }
    b3s[t] = b3[t];
    W4s[t] = W4[t];

    const int b0 = blockIdx.x * 16;
    for (int i = t; i < 16 * 132; i += 128) {
        const int bi = i / 132, k = i % 132, bb = b0 + bi;
        float v = 0.f;
        if (bb < B)
            v = (k < 128) ? dec_f(g_gf[bb * 128 + k]) : cond[bb * 4 + (k - 128)];
        in_s[bi * 132 + k] = v;
    }
    __syncthreads();

    const int j = t;
    for (int i = 0; i < 16; i++) {
        float acc = b3s[j];
        #pragma unroll 4
        for (int k = 0; k < 132; k++) acc += in_s[i * 132 + k] * W3s[k * 128 + j];
        hid_s[i * 128 + j] = lrelu(acc);
    }
    __syncthreads();

    const int i = t >> 3, g = t & 7;
    float acc = 0.f;
    #pragma unroll
    for (int q = 0; q < 16; q++) acc += hid_s[i * 128 + g * 16 + q] * W4s[g * 16 + q];
    acc += __shfl_down_sync(0xFFFFFFFFu, acc, 4, 8);
    acc += __shfl_down_sync(0xFFFFFFFFu, acc, 2, 8);
    acc += __shfl_down_sync(0xFFFFFFFFu, acc, 1, 8);
    if (g == 0 && (b0 + i) < B) out[b0 + i] = acc + b4[0];
}

// ---------------------------------------------------------------------------
extern "C" void kernel_launch(void* const* d_in, const int* in_sizes, int n_in,
                              void* d_out, int out_size)
{
    const float* fm   = (const float*)d_in[0];
    const int*   bi   = (const int*)  d_in[1];
    const float* cond = (const float*)d_in[2];
    const int base = (n_in >= 12) ? 4 : 3;
    const float* W1 = (const float*)d_in[base + 0];
    const float* b1 = (const float*)d_in[base + 1];
    const float* W2 = (const float*)d_in[base + 2];
    const float* b2 = (const float*)d_in[base + 3];
    const float* W3 = (const float*)d_in[base + 4];
    const float* b3 = (const float*)d_in[base + 5];
    const float* W4 = (const float*)d_in[base + 6];
    const float* b4 = (const float*)d_in[base + 7];

    const int N = in_sizes[0] / 3;
    const int B = in_sizes[2] / 4;
    float* out = (float*)d_out;

    cudaFuncSetAttribute(point_kernel,
                         cudaFuncAttributeMaxDynamicSharedMemorySize, SMEM_BYTES);
    const int SMEM_B = 21312 * 4;
    cudaFuncSetAttribute(decision_kernel,
                         cudaFuncAttributeMaxDynamicSharedMemorySize, SMEM_B);

    const int total_gf = B * 128;
    init_gf_kernel<<<(total_gf + 255) / 256, 256>>>(total_gf);

    const int numTiles = (N + 127) / 128;
    point_kernel<<<296, 256, SMEM_BYTES>>>(fm, bi, cond, W1, b1, W2, b2, N, numTiles);

    decision_kernel<<<(B + 15) / 16, 128, SMEM_B>>>(cond, W3, b3, W4, b4, out, B);
}

// round 4
// speedup vs baseline: 2.4338x; 1.4377x over previous
#include <cuda_runtime.h>
#include <cuda_bf16.h>
#include <cstdint>

#define NEG_INIT -1.0e9f

// ---------------------------------------------------------------------------
__device__ __forceinline__ unsigned enc_f(float f) {
    unsigned u = __float_as_uint(f);
    return (u & 0x80000000u) ? ~u : (u | 0x80000000u);
}
__device__ __forceinline__ float dec_f(unsigned e) {
    unsigned u = (e & 0x80000000u) ? (e & 0x7FFFFFFFu) : ~e;
    return __uint_as_float(u);
}
__device__ __forceinline__ float lrelu(float x) { return x >= 0.f ? x : 0.2f * x; }

__device__ unsigned g_gf[16384 * 128];   // encoded global_feats scratch (8 MB)

__device__ __forceinline__ uint32_t smem_u32(const void* p) {
    uint32_t a;
    asm("{ .reg .u64 t; cvta.to.shared.u64 t, %1; cvt.u32.u64 %0, t; }" : "=r"(a) : "l"(p));
    return a;
}

#define SWZ(x) ((x) ^ (((x) >> 3) & 0x70))

__device__ __forceinline__ void ldsm4(unsigned r[4], uint32_t addr) {
    asm volatile("ldmatrix.sync.aligned.m8n8.x4.shared.b16 {%0,%1,%2,%3}, [%4];"
                 : "=r"(r[0]), "=r"(r[1]), "=r"(r[2]), "=r"(r[3]) : "r"(addr));
}
__device__ __forceinline__ void hmma(float d[4], const unsigned a[4],
                                     unsigned b0, unsigned b1) {
    asm volatile(
        "mma.sync.aligned.m16n8k16.row.col.f32.bf16.bf16.f32 "
        "{%0,%1,%2,%3}, {%4,%5,%6,%7}, {%8,%9}, {%0,%1,%2,%3};"
        : "+f"(d[0]), "+f"(d[1]), "+f"(d[2]), "+f"(d[3])
        : "r"(a[0]), "r"(a[1]), "r"(a[2]), "r"(a[3]), "r"(b0), "r"(b1));
}

__device__ __forceinline__ unsigned pack_bf16(float a, float b) {
    __nv_bfloat16 ha = __float2bfloat16(a), hb = __float2bfloat16(b);
    return ((unsigned)__bfloat16_as_ushort(hb) << 16) | __bfloat16_as_ushort(ha);
}
__device__ __forceinline__ unsigned cvt_bf16x2(float lo, float hi) {
    unsigned r;
    asm("cvt.rn.bf16x2.f32 %0, %1, %2;" : "=r"(r) : "f"(hi), "f"(lo));
    return r;
}

// ---------------------------------------------------------------------------
// SMEM layout (bytes)
// ---------------------------------------------------------------------------
#define OFF_BHI   0          // [128n][64k] bf16, SW128, 16384 B
#define OFF_BLO   16384
#define OFF_AHI   32768      // [128m][64k] bf16, SW128
#define OFF_ALO   49152
#define OFF_W1    65536      // 448 floats
#define OFF_B1    67328      // 64 floats
#define OFF_B2    67584      // 128 floats
#define OFF_BIDX  68096      // 128 ints
#define OFF_COND  68608      // 128*4 floats
#define OFF_FM    70656      // 128*3 floats
#define SMEM_BYTES 72192

// ---------------------------------------------------------------------------
__global__ void init_gf_kernel(int total4) {
    int i = blockIdx.x * blockDim.x + threadIdx.x;
    if (i < total4) {
        unsigned e = enc_f(NEG_INIT);
        ((uint4*)g_gf)[i] = make_uint4(e, e, e, e);
    }
}

// ---------------------------------------------------------------------------
// Persistent fused point kernel: layer1 (FFMA) + layer2 (HMMA bf16-split)
// + in-register segmented max.  256 threads, grid = 296.
// ---------------------------------------------------------------------------
__global__ __launch_bounds__(256, 2) void point_kernel(
    const float* __restrict__ fm,   const int* __restrict__ bidx,
    const float* __restrict__ cond, const float* __restrict__ W1,
    const float* __restrict__ b1,   const float* __restrict__ W2,
    const float* __restrict__ b2,   int N, int numTiles)
{
    extern __shared__ char smem[];
    const uint32_t sbase = smem_u32(smem);
    const int t    = threadIdx.x;
    const int wid  = t >> 5;
    const int lane = t & 31;

    float* W1s   = (float*)(smem + OFF_W1);
    float* b1s   = (float*)(smem + OFF_B1);
    float* b2s   = (float*)(smem + OFF_B2);
    int*   bix   = (int*)(smem + OFF_BIDX);
    float* conds = (float*)(smem + OFF_COND);
    float* fms   = (float*)(smem + OFF_FM);

    // ---- one-time staging: W2 -> B hi/lo ([n][k] bf16, SW128), W1, biases ----
    for (int e = t; e < 4096; e += 256) {
        int n = e >> 5, k2 = e & 31;
        float w0 = W2[(2 * k2) * 128 + n];
        float w1 = W2[(2 * k2 + 1) * 128 + n];
        __nv_bfloat16 h0 = __float2bfloat16(w0), h1 = __float2bfloat16(w1);
        float r0 = w0 - __bfloat162float(h0), r1 = w1 - __bfloat162float(h1);
        unsigned hi = ((unsigned)__bfloat16_as_ushort(h1) << 16) | __bfloat16_as_ushort(h0);
        unsigned lo = pack_bf16(r0, r1);
        unsigned off = (unsigned)(n * 128 + k2 * 4);
        *(unsigned*)(smem + OFF_BHI + SWZ(off)) = hi;
        *(unsigned*)(smem + OFF_BLO + SWZ(off)) = lo;
    }
    for (int i = t; i < 448; i += 256) W1s[i] = W1[i];
    if (t < 64)  b1s[t] = b1[t];
    if (t < 128) b2s[t] = b2[t];

    const int m    = t & 127;
    const int half = t >> 7;
    const int wm   = wid & 3;      // m 32-slice
    const int wn   = wid >> 2;     // n 64-slice

    for (int tile = blockIdx.x; tile < numTiles; tile += gridDim.x) {
        const int rbase = tile * 128;
        __syncthreads();           // prior epilogue reads of bix / A ldsm done

        // ---- phase A: stage inputs ----
        for (int i = t; i < 384; i += 256) {
            int g = rbase * 3 + i;
            fms[i] = (g < N * 3) ? fm[g] : 0.f;
        }
        if (t < 128) {
            int row = rbase + t;
            int b = (row < N) ? bidx[row] : -1;
            bix[t] = b;
            float4 c4 = make_float4(0.f, 0.f, 0.f, 0.f);
            if (b >= 0) c4 = *(const float4*)(cond + b * 4);
            *(float4*)(conds + t * 4) = c4;
        }
        __syncthreads();

        // ---- phase B: layer 1 (each thread: row m, 32 cols) + split-store ----
        {
            float in[7];
            in[0] = fms[m * 3 + 0]; in[1] = fms[m * 3 + 1]; in[2] = fms[m * 3 + 2];
            in[3] = conds[m * 4 + 0]; in[4] = conds[m * 4 + 1];
            in[5] = conds[m * 4 + 2]; in[6] = conds[m * 4 + 3];
            float h[32];
            #pragma unroll
            for (int jj = 0; jj < 32; jj++) {
                const int j = (half << 5) + jj;
                float a = b1s[j];
                #pragma unroll
                for (int k = 0; k < 7; k++) a += in[k] * W1s[k * 64 + j];
                h[jj] = lrelu(a);
            }
            // truncation split: hi = x & 0xFFFF0000 (exact in regs), lo = x - hi
            #pragma unroll
            for (int q = 0; q < 4; q++) {
                uint4 uhi, ulo;
                unsigned u[8]; float lv[8];
                #pragma unroll
                for (int e = 0; e < 8; e++) {
                    float x = h[q * 8 + e];
                    u[e] = __float_as_uint(x);
                    lv[e] = x - __uint_as_float(u[e] & 0xFFFF0000u);
                }
                uhi.x = __byte_perm(u[0], u[1], 0x7632);
                uhi.y = __byte_perm(u[2], u[3], 0x7632);
                uhi.z = __byte_perm(u[4], u[5], 0x7632);
                uhi.w = __byte_perm(u[6], u[7], 0x7632);
                ulo.x = cvt_bf16x2(lv[0], lv[1]);
                ulo.y = cvt_bf16x2(lv[2], lv[3]);
                ulo.z = cvt_bf16x2(lv[4], lv[5]);
                ulo.w = cvt_bf16x2(lv[6], lv[7]);
                const int chunk = ((half << 2) + q) ^ (m & 7);
                *(uint4*)(smem + OFF_AHI + m * 128 + (chunk << 4)) = uhi;
                *(uint4*)(smem + OFF_ALO + m * 128 + (chunk << 4)) = ulo;
            }
        }
        __syncthreads();

        // ---- phase C: layer 2 GEMM (HMMA, bf16 split x3) ----
        float d[2][8][4];
        #pragma unroll
        for (int mi = 0; mi < 2; mi++)
            #pragma unroll
            for (int ni = 0; ni < 8; ni++)
                #pragma unroll
                for (int e = 0; e < 4; e++) d[mi][ni][e] = 0.f;

        #pragma unroll
        for (int ks = 0; ks < 4; ks++) {
            int arow = (wm << 5) + (lane & 15);
            int akch = (ks << 1) + (lane >> 4);
            uint32_t aoff = (uint32_t)(arow * 128 + (((akch ^ (arow & 7)) & 7) << 4));
            unsigned ahi[2][4], alo[2][4];
            ldsm4(ahi[0], sbase + OFF_AHI + aoff);
            ldsm4(ahi[1], sbase + OFF_AHI + aoff + 16 * 128);
            ldsm4(alo[0], sbase + OFF_ALO + aoff);
            ldsm4(alo[1], sbase + OFF_ALO + aoff + 16 * 128);
            int brow = (wn << 6) + (lane & 7) + ((lane >> 4) << 3);
            int bkch = (ks << 1) + ((lane >> 3) & 1);
            uint32_t boff = (uint32_t)(brow * 128 + (((bkch ^ (brow & 7)) & 7) << 4));
            unsigned bf[4][4];
            #pragma unroll
            for (int g = 0; g < 4; g++) ldsm4(bf[g], sbase + OFF_BHI + boff + g * 2048);
            #pragma unroll
            for (int g = 0; g < 4; g++) {
                #pragma unroll
                for (int mi = 0; mi < 2; mi++) {
                    hmma(d[mi][2 * g + 0], ahi[mi], bf[g][0], bf[g][1]);
                    hmma(d[mi][2 * g + 1], ahi[mi], bf[g][2], bf[g][3]);
                    hmma(d[mi][2 * g + 0], alo[mi], bf[g][0], bf[g][1]);
                    hmma(d[mi][2 * g + 1], alo[mi], bf[g][2], bf[g][3]);
                }
            }
            #pragma unroll
            for (int g = 0; g < 4; g++) ldsm4(bf[g], sbase + OFF_BLO + boff + g * 2048);
            #pragma unroll
            for (int g = 0; g < 4; g++) {
                #pragma unroll
                for (int mi = 0; mi < 2; mi++) {
                    hmma(d[mi][2 * g + 0], ahi[mi], bf[g][0], bf[g][1]);
                    hmma(d[mi][2 * g + 1], ahi[mi], bf[g][2], bf[g][3]);
                }
            }
        }

        // ---- phase D: in-register segmented max + atomics (per warp) ----
        {
            const int base = wm << 5;
            const int rA   = lane >> 2;           // 0..7, this thread's row group
            const int blast = bix[base + 31];
            int rstart = 0;
            while (rstart < 32) {
                const int cur = bix[base + rstart];
                int rend;
                if (blast == cur) rend = 32;
                else {
                    rend = rstart + 1;
                    while (rend < 32 && bix[base + rend] == cur) rend++;
                }
                // predicated max of this thread's 4 rows into acc[16]
                const bool p0 = (rA      >= rstart) && (rA      < rend);
                const bool p1 = (rA + 8  >= rstart) && (rA + 8  < rend);
                const bool p2 = (rA + 16 >= rstart) && (rA + 16 < rend);
                const bool p3 = (rA + 24 >= rstart) && (rA + 24 < rend);
                float acc[16];
                #pragma unroll
                for (int ni = 0; ni < 8; ni++) {
                    float a0 = NEG_INIT, a1 = NEG_INIT;
                    if (p0) { a0 = d[0][ni][0]; a1 = d[0][ni][1]; }
                    if (p1) { a0 = fmaxf(a0, d[0][ni][2]); a1 = fmaxf(a1, d[0][ni][3]); }
                    if (p2) { a0 = fmaxf(a0, d[1][ni][0]); a1 = fmaxf(a1, d[1][ni][1]); }
                    if (p3) { a0 = fmaxf(a0, d[1][ni][2]); a1 = fmaxf(a1, d[1][ni][3]); }
                    acc[2 * ni] = a0; acc[2 * ni + 1] = a1;
                }
                #pragma unroll
                for (int q = 0; q < 16; q++) {
                    acc[q] = fmaxf(acc[q], __shfl_xor_sync(0xFFFFFFFFu, acc[q], 4));
                    acc[q] = fmaxf(acc[q], __shfl_xor_sync(0xFFFFFFFFu, acc[q], 8));
                    acc[q] = fmaxf(acc[q], __shfl_xor_sync(0xFFFFFFFFu, acc[q], 16));
                }
                if (lane < 4 && cur >= 0) {
                    #pragma unroll
                    for (int ni = 0; ni < 8; ni++) {
                        const int c = (wn << 6) + (ni << 3) + (lane << 1);
                        float y0 = lrelu(acc[2 * ni]     + b2s[c]);
                        float y1 = lrelu(acc[2 * ni + 1] + b2s[c + 1]);
                        atomicMax(&g_gf[(cur << 7) + c],     enc_f(y0));
                        atomicMax(&g_gf[(cur << 7) + c + 1], enc_f(y1));
                    }
                }
                rstart = rend;
            }
        }
    }
}

// ---------------------------------------------------------------------------
// Decision MLP (unchanged)
// ---------------------------------------------------------------------------
__global__ __launch_bounds__(128) void decision_kernel(
    const float* __restrict__ cond, const float* __restrict__ W3,
    const float* __restrict__ b3,   const float* __restrict__ W4,
    const float* __restrict__ b4,   float* __restrict__ out, int B)
{
    extern __shared__ float sm[];
    float* W3s   = sm;
    float* b3s   = W3s + 16896;
    float* W4s   = b3s + 128;
    float* in_s  = W4s + 128;
    float* hid_s = in_s + 2112;

    const int t = threadIdx.x;
    {
        const float4* src = (const float4*)W3;
        float4* dst = (float4*)W3s;
        for (int i = t; i < 4224; i += 128) dst[i] = src[i];
    }
    b3s[t] = b3[t];
    W4s[t] = W4[t];

    const int b0 = blockIdx.x * 16;
    for (int i = t; i < 16 * 132; i += 128) {
        const int bi = i / 132, k = i % 132, bb = b0 + bi;
        float v = 0.f;
        if (bb < B)
            v = (k < 128) ? dec_f(g_gf[bb * 128 + k]) : cond[bb * 4 + (k - 128)];
        in_s[bi * 132 + k] = v;
    }
    __syncthreads();

    const int j = t;
    for (int i = 0; i < 16; i++) {
        float acc = b3s[j];
        #pragma unroll 4
        for (int k = 0; k < 132; k++) acc += in_s[i * 132 + k] * W3s[k * 128 + j];
        hid_s[i * 128 + j] = lrelu(acc);
    }
    __syncthreads();

    const int i = t >> 3, g = t & 7;
    float acc = 0.f;
    #pragma unroll
    for (int q = 0; q < 16; q++) acc += hid_s[i * 128 + g * 16 + q] * W4s[g * 16 + q];
    acc += __shfl_down_sync(0xFFFFFFFFu, acc, 4, 8);
    acc += __shfl_down_sync(0xFFFFFFFFu, acc, 2, 8);
    acc += __shfl_down_sync(0xFFFFFFFFu, acc, 1, 8);
    if (g == 0 && (b0 + i) < B) out[b0 + i] = acc + b4[0];
}

// ---------------------------------------------------------------------------
extern "C" void kernel_launch(void* const* d_in, const int* in_sizes, int n_in,
                              void* d_out, int out_size)
{
    const float* fm   = (const float*)d_in[0];
    const int*   bi   = (const int*)  d_in[1];
    const float* cond = (const float*)d_in[2];
    const int base = (n_in >= 12) ? 4 : 3;
    const float* W1 = (const float*)d_in[base + 0];
    const float* b1 = (const float*)d_in[base + 1];
    const float* W2 = (const float*)d_in[base + 2];
    const float* b2 = (const float*)d_in[base + 3];
    const float* W3 = (const float*)d_in[base + 4];
    const float* b3 = (const float*)d_in[base + 5];
    const float* W4 = (const float*)d_in[base + 6];
    const float* b4 = (const float*)d_in[base + 7];

    const int N = in_sizes[0] / 3;
    const int B = in_sizes[2] / 4;
    float* out = (float*)d_out;

    cudaFuncSetAttribute(point_kernel,
                         cudaFuncAttributeMaxDynamicSharedMemorySize, SMEM_BYTES);
    const int SMEM_B = 21312 * 4;
    cudaFuncSetAttribute(decision_kernel,
                         cudaFuncAttributeMaxDynamicSharedMemorySize, SMEM_B);

    const int total4 = B * 128 / 4;
    init_gf_kernel<<<(total4 + 255) / 256, 256>>>(total4);

    const int numTiles = (N + 127) / 128;
    point_kernel<<<296, 256, SMEM_BYTES>>>(fm, bi, cond, W1, b1, W2, b2, N, numTiles);

    decision_kernel<<<(B + 15) / 16, 128, SMEM_B>>>(cond, W3, b3, W4, b4, out, B);
}